// round 9
// baseline (speedup 1.0000x reference)
#include <cuda_runtime.h>
#include <cuda_fp16.h>
#include <math.h>

#define NN 50000
#define EE 1600000
#define ETOT (EE + NN)
#define G64BLK ((NN + 127) / 128)
#define EBLK ((ETOT + 255) / 256)

// ---------------- scratch ----------------
__device__ uint4  g_h16v[NN * 8];    // fp16 h, 16B-aligned (64 halves per node)
__device__ float  g_x2[NN * 64];
__device__ float  g_als[NN * 4];
__device__ float  g_ald[NN * 4];
__device__ float  g_acc[NN * 16];
__device__ int    g_deg[NN];
__device__ int    g_off[NN + 1];
__device__ int    g_cur[NN];
__device__ int    g_csr[ETOT];

// ================= CSR build =================
__global__ void hist_kernel(const int* __restrict__ ei) {
    int e = blockIdx.x * blockDim.x + threadIdx.x;
    if (e >= ETOT) return;
    int d = (e < EE) ? ei[EE + e] : (e - EE);
    atomicAdd(&g_deg[d], 1);
}

__global__ void scan_kernel() {
    __shared__ int partial[1024];
    int t = threadIdx.x;
    const int C = (NN + 1023) / 1024;
    int b0 = t * C;
    int b1 = min(b0 + C, NN);
    int sum = 0;
    for (int i = b0; i < b1; i++) sum += g_deg[i];
    partial[t] = sum;
    __syncthreads();
    for (int off = 1; off < 1024; off <<= 1) {
        int v = (t >= off) ? partial[t - off] : 0;
        __syncthreads();
        partial[t] += v;
        __syncthreads();
    }
    int run = (t == 0) ? 0 : partial[t - 1];
    for (int i = b0; i < b1; i++) {
        g_off[i] = run;
        g_cur[i] = run;
        run += g_deg[i];
    }
    if (t == 1023) g_off[NN] = run;
}

// ===== fused: layer-1 GEMM (blocks [0, G64BLK)) || CSR scatter (rest) =====
__global__ void __launch_bounds__(256)
fused_gemm1_scatter(const float* __restrict__ X, const float* __restrict__ W,
                    const float* __restrict__ a_s, const float* __restrict__ a_d,
                    const int* __restrict__ ei) {
    constexpr int IN = 128;
    constexpr int KT = 32;
    constexpr int SXS = 132;
    __shared__ float sW[KT][64];
    __shared__ float sX2[KT][SXS];
    int t = threadIdx.x;

    if (blockIdx.x >= G64BLK) {
        int e = (blockIdx.x - G64BLK) * 256 + t;
        if (e < ETOT) {
            int s, d;
            if (e < EE) { s = ei[e]; d = ei[EE + e]; } else { s = e - EE; d = s; }
            int pos = atomicAdd(&g_cur[d], 1);
            g_csr[pos] = s;
        }
        return;
    }

    int tx = t & 15, ty = t >> 4;
    int row0 = blockIdx.x * 128;
    float acc[8][4];
#pragma unroll
    for (int r = 0; r < 8; r++)
#pragma unroll
        for (int c = 0; c < 4; c++) acc[r][c] = 0.f;

    for (int kt = 0; kt < IN; kt += KT) {
#pragma unroll
        for (int i = t; i < KT * 16; i += 256) {
            int kk = i >> 4;
            int c4 = (i & 15) << 2;
            *(float4*)&sW[kk][c4] = *(const float4*)&W[(kt + kk) * 64 + c4];
        }
#pragma unroll
        for (int i = t; i < 128 * (KT / 4); i += 256) {
            int r = i >> 3;
            int k4 = (i & 7) << 2;
            int gr = row0 + r;
            float4 v = (gr < NN) ? *(const float4*)&X[gr * IN + kt + k4]
                                 : make_float4(0.f, 0.f, 0.f, 0.f);
            sX2[k4 + 0][r] = v.x;
            sX2[k4 + 1][r] = v.y;
            sX2[k4 + 2][r] = v.z;
            sX2[k4 + 3][r] = v.w;
        }
        __syncthreads();
#pragma unroll
        for (int k = 0; k < KT; k++) {
            float4 w4 = *(float4*)&sW[k][tx * 4];
            float4 xa = *(float4*)&sX2[k][ty * 8];
            float4 xb = *(float4*)&sX2[k][ty * 8 + 4];
            float xr[8] = {xa.x, xa.y, xa.z, xa.w, xb.x, xb.y, xb.z, xb.w};
#pragma unroll
            for (int r = 0; r < 8; r++) {
                acc[r][0] += xr[r] * w4.x;
                acc[r][1] += xr[r] * w4.y;
                acc[r][2] += xr[r] * w4.z;
                acc[r][3] += xr[r] * w4.w;
            }
        }
        __syncthreads();
    }

    int h = tx >> 2;
    float4 asv = *(const float4*)&a_s[h * 16 + (tx & 3) * 4];
    float4 adv = *(const float4*)&a_d[h * 16 + (tx & 3) * 4];
    __half2* h2out = (__half2*)g_h16v;
#pragma unroll
    for (int r = 0; r < 8; r++) {
        int gr = row0 + ty * 8 + r;
        float ps = acc[r][0] * asv.x + acc[r][1] * asv.y + acc[r][2] * asv.z + acc[r][3] * asv.w;
        float pd = acc[r][0] * adv.x + acc[r][1] * adv.y + acc[r][2] * adv.z + acc[r][3] * adv.w;
        ps += __shfl_xor_sync(0xffffffffu, ps, 1);
        ps += __shfl_xor_sync(0xffffffffu, ps, 2);
        pd += __shfl_xor_sync(0xffffffffu, pd, 1);
        pd += __shfl_xor_sync(0xffffffffu, pd, 2);
        if (gr < NN) {
            h2out[(gr * 64 + tx * 4) >> 1] = __floats2half2_rn(acc[r][0], acc[r][1]);
            h2out[((gr * 64 + tx * 4) >> 1) + 1] = __floats2half2_rn(acc[r][2], acc[r][3]);
            if ((tx & 3) == 0) {
                g_als[gr * 4 + h] = ps;
                g_ald[gr * 4 + h] = pd;
            }
        }
    }
}

// ------- GEMM 64-wide (layer 2), 128-row tile, fused al + fp16 out ----
template <int IN>
__global__ void __launch_bounds__(256)
gemm64(const float* __restrict__ X, const float* __restrict__ W,
       const float* __restrict__ a_s, const float* __restrict__ a_d) {
    constexpr int KT = 32;
    constexpr int SXS = 132;
    __shared__ float sW[KT][64];
    __shared__ float sX2[KT][SXS];
    int t = threadIdx.x;
    int tx = t & 15, ty = t >> 4;
    int row0 = blockIdx.x * 128;
    float acc[8][4];
#pragma unroll
    for (int r = 0; r < 8; r++)
#pragma unroll
        for (int c = 0; c < 4; c++) acc[r][c] = 0.f;

    for (int kt = 0; kt < IN; kt += KT) {
#pragma unroll
        for (int i = t; i < KT * 16; i += 256) {
            int kk = i >> 4;
            int c4 = (i & 15) << 2;
            *(float4*)&sW[kk][c4] = *(const float4*)&W[(kt + kk) * 64 + c4];
        }
#pragma unroll
        for (int i = t; i < 128 * (KT / 4); i += 256) {
            int r = i >> 3;
            int k4 = (i & 7) << 2;
            int gr = row0 + r;
            float4 v = (gr < NN) ? *(const float4*)&X[gr * IN + kt + k4]
                                 : make_float4(0.f, 0.f, 0.f, 0.f);
            sX2[k4 + 0][r] = v.x;
            sX2[k4 + 1][r] = v.y;
            sX2[k4 + 2][r] = v.z;
            sX2[k4 + 3][r] = v.w;
        }
        __syncthreads();
#pragma unroll
        for (int k = 0; k < KT; k++) {
            float4 w4 = *(float4*)&sW[k][tx * 4];
            float4 xa = *(float4*)&sX2[k][ty * 8];
            float4 xb = *(float4*)&sX2[k][ty * 8 + 4];
            float xr[8] = {xa.x, xa.y, xa.z, xa.w, xb.x, xb.y, xb.z, xb.w};
#pragma unroll
            for (int r = 0; r < 8; r++) {
                acc[r][0] += xr[r] * w4.x;
                acc[r][1] += xr[r] * w4.y;
                acc[r][2] += xr[r] * w4.z;
                acc[r][3] += xr[r] * w4.w;
            }
        }
        __syncthreads();
    }

    int h = tx >> 2;
    float4 asv = *(const float4*)&a_s[h * 16 + (tx & 3) * 4];
    float4 adv = *(const float4*)&a_d[h * 16 + (tx & 3) * 4];
    __half2* h2out = (__half2*)g_h16v;
#pragma unroll
    for (int r = 0; r < 8; r++) {
        int gr = row0 + ty * 8 + r;
        float ps = acc[r][0] * asv.x + acc[r][1] * asv.y + acc[r][2] * asv.z + acc[r][3] * asv.w;
        float pd = acc[r][0] * adv.x + acc[r][1] * adv.y + acc[r][2] * adv.z + acc[r][3] * adv.w;
        ps += __shfl_xor_sync(0xffffffffu, ps, 1);
        ps += __shfl_xor_sync(0xffffffffu, ps, 2);
        pd += __shfl_xor_sync(0xffffffffu, pd, 1);
        pd += __shfl_xor_sync(0xffffffffu, pd, 2);
        if (gr < NN) {
            h2out[(gr * 64 + tx * 4) >> 1] = __floats2half2_rn(acc[r][0], acc[r][1]);
            h2out[((gr * 64 + tx * 4) >> 1) + 1] = __floats2half2_rn(acc[r][2], acc[r][3]);
            if ((tx & 3) == 0) {
                g_als[gr * 4 + h] = ps;
                g_ald[gr * 4 + h] = pd;
            }
        }
    }
}

// ------- GEMM layer 3 (64->16): fused al epilogue, fp16-only output -------
__global__ void gemm16(const float* __restrict__ X, const float* __restrict__ W,
                       const float* __restrict__ a_s, const float* __restrict__ a_d) {
    constexpr int IN = 64, OUT = 16;
    constexpr int RB = 64;
    __shared__ float sW[IN * OUT];
    __shared__ float sX[RB * IN];
    int t = threadIdx.x;
    int tx = t & 15, ty = t >> 4;
    int row0 = blockIdx.x * RB;

    for (int i = t; i < IN * OUT; i += 256) sW[i] = W[i];
    for (int i = t; i < RB * IN; i += 256) {
        int r = row0 + i / IN;
        sX[i] = (r < NN) ? X[r * IN + (i % IN)] : 0.f;
    }
    __syncthreads();

    float acc[4];
#pragma unroll
    for (int rr = 0; rr < 4; rr++) acc[rr] = 0.f;
    const float* xs = &sX[ty * 4 * IN];
    for (int k = 0; k < IN; k++) {
        float wv = sW[k * OUT + tx];
#pragma unroll
        for (int rr = 0; rr < 4; rr++) acc[rr] += xs[rr * IN + k] * wv;
    }
    float asx = __ldg(&a_s[tx]), adx = __ldg(&a_d[tx]);
    __half* h16 = (__half*)g_h16v;
#pragma unroll
    for (int rr = 0; rr < 4; rr++) {
        int r = row0 + ty * 4 + rr;
        float ps = acc[rr] * asx;
        float pd = acc[rr] * adx;
#pragma unroll
        for (int off = 1; off < 16; off <<= 1) {
            ps += __shfl_xor_sync(0xffffffffu, ps, off);
            pd += __shfl_xor_sync(0xffffffffu, pd, off);
        }
        if (r < NN) {
            h16[r * OUT + tx] = __float2half_rn(acc[rr]);
            if (tx == 0) {
                g_als[r] = ps;
                g_ald[r] = pd;
            }
        }
    }
}

__device__ __forceinline__ float lrelu_exp(float v) {
    v = (v > 0.f) ? v : 0.2f * v;
    return __expf(v);
}

// ============ fused gather-aggregation, 64-wide (layers 1 & 2) ============
// warp per dst node; 4 edge-groups of 8 lanes; lane owns 8 cols via LDG.128.
// head = (lane&7)>>1 (8-col group lies within one 16-col head).
__global__ void __launch_bounds__(256)
agg64(const float* __restrict__ b,
      const float* __restrict__ gg, const float* __restrict__ bb,
      const float* __restrict__ mm, const float* __restrict__ vv,
      float* __restrict__ xnext) {
    __shared__ float2 sh_sex[8][4][36];   // [warp][head][edge], padded: conflict-free
    int w = threadIdx.x >> 5;
    int lane = threadIdx.x & 31;
    int n = (blockIdx.x * blockDim.x + threadIdx.x) >> 5;
    if (n >= NN) return;
    int eg = lane >> 3;        // edge group 0..3
    int cg = lane & 7;         // col group: cols 8*cg .. 8*cg+7
    int h = cg >> 1;           // head of those cols
    float4 ad4 = *(const float4*)&g_ald[n * 4];
    float acc[8];
#pragma unroll
    for (int i = 0; i < 8; i++) acc[i] = 0.f;
    float den = 0.f;
    const uint4* ph4 = (const uint4*)g_h16v;
    int beg = g_off[n], end = g_off[n + 1];
    for (int base = beg; base < end; base += 32) {
        int idx = base + lane;
        bool valid = idx < end;
        int s = valid ? g_csr[idx] : 0;
        float4 as4 = *(const float4*)&g_als[s * 4];
        float sf = __int_as_float(s);
        float e0 = valid ? lrelu_exp(as4.x + ad4.x) : 0.f;
        float e1 = valid ? lrelu_exp(as4.y + ad4.y) : 0.f;
        float e2 = valid ? lrelu_exp(as4.z + ad4.z) : 0.f;
        float e3 = valid ? lrelu_exp(as4.w + ad4.w) : 0.f;
        __syncwarp();
        sh_sex[w][0][lane] = make_float2(sf, e0);
        sh_sex[w][1][lane] = make_float2(sf, e1);
        sh_sex[w][2][lane] = make_float2(sf, e2);
        sh_sex[w][3][lane] = make_float2(sf, e3);
        __syncwarp();
        int nk4 = (min(32, end - base) + 3) & ~3;
        for (int j0 = 0; j0 < nk4; j0 += 4) {
            float2 p = sh_sex[w][h][j0 + eg];
            int sj = __float_as_int(p.x);
            float ex = p.y;
            uint4 v = __ldg(&ph4[sj * 8 + cg]);
            float2 f0 = __half22float2(*(__half2*)&v.x);
            float2 f1 = __half22float2(*(__half2*)&v.y);
            float2 f2 = __half22float2(*(__half2*)&v.z);
            float2 f3 = __half22float2(*(__half2*)&v.w);
            acc[0] += ex * f0.x; acc[1] += ex * f0.y;
            acc[2] += ex * f1.x; acc[3] += ex * f1.y;
            acc[4] += ex * f2.x; acc[5] += ex * f2.y;
            acc[6] += ex * f3.x; acc[7] += ex * f3.y;
            den += ex;
        }
    }
    // reduce across the 4 edge groups (lanes with same cg)
#pragma unroll
    for (int off = 8; off <= 16; off <<= 1) {
#pragma unroll
        for (int i = 0; i < 8; i++) acc[i] += __shfl_xor_sync(0xffffffffu, acc[i], off);
        den += __shfl_xor_sync(0xffffffffu, den, off);
    }
    if (lane < 8) {
        float inv = 1.f / (den + 1e-16f);
        int c0 = 8 * cg;
        float o[8];
#pragma unroll
        for (int i = 0; i < 8; i++) {
            int col = c0 + i;
            float y = (acc[i] * inv + __ldg(&b[col]) - __ldg(&mm[col])) *
                          rsqrtf(__ldg(&vv[col]) + 1e-5f) * __ldg(&gg[col]) +
                      __ldg(&bb[col]);
            o[i] = fmaxf(y, 0.f);
        }
        *(float4*)&xnext[n * 64 + c0] = make_float4(o[0], o[1], o[2], o[3]);
        *(float4*)&xnext[n * 64 + c0 + 4] = make_float4(o[4], o[5], o[6], o[7]);
    }
}

// ============ fused gather-aggregation, 16-wide (layer 3) ============
__global__ void __launch_bounds__(256)
agg16() {
    __shared__ float2 sh_sex[8][33];
    int w = threadIdx.x >> 5;
    int lane = threadIdx.x & 31;
    int n = (blockIdx.x * blockDim.x + threadIdx.x) >> 5;
    if (n >= NN) return;
    int q = lane >> 3;        // edge-group 0..3
    int c2 = lane & 7;        // half2 column index
    float ad = g_ald[n];
    float accx = 0.f, accy = 0.f, den = 0.f;
    const __half2* ph2 = (const __half2*)g_h16v;
    int beg = g_off[n], end = g_off[n + 1];
    for (int base = beg; base < end; base += 32) {
        int idx = base + lane;
        bool valid = idx < end;
        int s = valid ? g_csr[idx] : 0;
        float ex = valid ? lrelu_exp(__ldg(&g_als[s]) + ad) : 0.f;
        __syncwarp();
        sh_sex[w][lane] = make_float2(__int_as_float(s), ex);
        __syncwarp();
        int nk4 = (min(32, end - base) + 3) & ~3;
        for (int j0 = 0; j0 < nk4; j0 += 4) {
            int j = j0 + q;
            float2 p = sh_sex[w][j];
            int sj = __float_as_int(p.x);
            float exj = p.y;
            float2 f = __half22float2(__ldg(&ph2[sj * 8 + c2]));
            accx += exj * f.x;
            accy += exj * f.y;
            den += exj;
        }
    }
    accx += __shfl_xor_sync(0xffffffffu, accx, 8);
    accx += __shfl_xor_sync(0xffffffffu, accx, 16);
    accy += __shfl_xor_sync(0xffffffffu, accy, 8);
    accy += __shfl_xor_sync(0xffffffffu, accy, 16);
    den += __shfl_xor_sync(0xffffffffu, den, 8);
    den += __shfl_xor_sync(0xffffffffu, den, 16);
    if (lane < 8) {
        float inv = 1.f / (den + 1e-16f);
        float2 o = make_float2(accx * inv, accy * inv);
        *(float2*)&g_acc[n * 16 + 2 * c2] = o;
    }
}

// ---------------- epilogue layer 3 ----------------
__global__ void ep3(const float* __restrict__ b3, const float* __restrict__ gg,
                    const float* __restrict__ bb, const float* __restrict__ mm,
                    const float* __restrict__ vv, const float* __restrict__ fw1,
                    const float* __restrict__ fb1, const float* __restrict__ fw2,
                    const float* __restrict__ fb2, float* __restrict__ out) {
    int n = blockIdx.x * blockDim.x + threadIdx.x;
    if (n >= NN) return;
    float t[16];
#pragma unroll
    for (int c = 0; c < 16; c++) {
        float y = (g_acc[n * 16 + c] + __ldg(&b3[c]) - __ldg(&mm[c])) *
                      rsqrtf(__ldg(&vv[c]) + 1e-5f) * __ldg(&gg[c]) +
                  __ldg(&bb[c]);
        t[c] = fmaxf(y, 0.f);
    }
    float o = __ldg(&fb2[0]);
#pragma unroll
    for (int oo = 0; oo < 8; oo++) {
        float z = __ldg(&fb1[oo]);
#pragma unroll
        for (int c = 0; c < 16; c++) z += t[c] * __ldg(&fw1[c * 8 + oo]);
        z = fmaxf(z, 0.f);
        o += z * __ldg(&fw2[oo]);
    }
    out[n] = o;
}

// ---------------- launch ----------------
extern "C" void kernel_launch(void* const* d_in, const int* in_sizes, int n_in,
                              void* d_out, int out_size) {
    const float* x = (const float*)d_in[0];
    const int* ei = (const int*)d_in[1];
    const float* W1 = (const float*)d_in[2];
    const float* as1 = (const float*)d_in[3];
    const float* ad1 = (const float*)d_in[4];
    const float* b1 = (const float*)d_in[5];
    const float* g1 = (const float*)d_in[6];
    const float* bb1 = (const float*)d_in[7];
    const float* m1 = (const float*)d_in[8];
    const float* v1 = (const float*)d_in[9];
    const float* W2 = (const float*)d_in[10];
    const float* as2 = (const float*)d_in[11];
    const float* ad2 = (const float*)d_in[12];
    const float* b2 = (const float*)d_in[13];
    const float* g2 = (const float*)d_in[14];
    const float* bb2 = (const float*)d_in[15];
    const float* m2 = (const float*)d_in[16];
    const float* v2 = (const float*)d_in[17];
    const float* W3 = (const float*)d_in[18];
    const float* as3 = (const float*)d_in[19];
    const float* ad3 = (const float*)d_in[20];
    const float* b3 = (const float*)d_in[21];
    const float* g3 = (const float*)d_in[22];
    const float* bb3 = (const float*)d_in[23];
    const float* m3 = (const float*)d_in[24];
    const float* v3 = (const float*)d_in[25];
    const float* fw1 = (const float*)d_in[26];
    const float* fb1 = (const float*)d_in[27];
    const float* fw2 = (const float*)d_in[28];
    const float* fb2 = (const float*)d_in[29];
    float* out = (float*)d_out;

    float* px2 = nullptr;
    int* pdeg = nullptr;
    cudaGetSymbolAddress((void**)&px2, g_x2);
    cudaGetSymbolAddress((void**)&pdeg, g_deg);

    const int TB = 256;
    int nblk = (NN + TB - 1) / TB;
    int aggblk = (NN * 32 + TB - 1) / TB;

    // ---- CSR: hist + scan, then scatter fused with layer-1 GEMM ----
    cudaMemsetAsync(pdeg, 0, NN * sizeof(int));
    hist_kernel<<<EBLK, TB>>>(ei);
    scan_kernel<<<1, 1024>>>();

    // ---- Layer 1 GEMM || CSR scatter ----
    fused_gemm1_scatter<<<G64BLK + EBLK, TB>>>(x, W1, as1, ad1, ei);
    agg64<<<aggblk, TB>>>(b1, g1, bb1, m1, v1, px2);

    // ---- Layer 2 ----
    gemm64<64><<<G64BLK, TB>>>(px2, W2, as2, ad2);
    agg64<<<aggblk, TB>>>(b2, g2, bb2, m2, v2, px2);

    // ---- Layer 3 ----
    gemm16<<<(NN + 63) / 64, TB>>>(px2, W3, as3, ad3);
    agg16<<<aggblk, TB>>>();
    ep3<<<nblk, TB>>>(b3, g3, bb3, m3, v3, fw1, fb1, fw2, fb2, out);
}

// round 10
// speedup vs baseline: 1.0670x; 1.0670x over previous
#include <cuda_runtime.h>
#include <cuda_fp16.h>
#include <math.h>

#define NN 50000
#define EE 1600000
#define ETOT (EE + NN)
#define G64BLK ((NN + 127) / 128)
#define EBLK ((ETOT + 255) / 256)

// ---------------- scratch ----------------
__device__ uint4  g_h16v[NN * 8];    // fp16 h, 16B-aligned (64 halves per node)
__device__ float  g_x2[NN * 64];
__device__ float  g_als[NN * 4];
__device__ float  g_ald[NN * 4];
__device__ float  g_acc[NN * 16];
__device__ int    g_deg[NN];
__device__ int    g_off[NN + 1];
__device__ int    g_cur[NN];
__device__ int    g_csr[ETOT];

// ================= CSR build =================
__global__ void hist_kernel(const int* __restrict__ ei) {
    int e = blockIdx.x * blockDim.x + threadIdx.x;
    if (e >= ETOT) return;
    int d = (e < EE) ? ei[EE + e] : (e - EE);
    atomicAdd(&g_deg[d], 1);
}

__global__ void scan_kernel() {
    __shared__ int partial[1024];
    int t = threadIdx.x;
    const int C = (NN + 1023) / 1024;
    int b0 = t * C;
    int b1 = min(b0 + C, NN);
    int sum = 0;
    for (int i = b0; i < b1; i++) sum += g_deg[i];
    partial[t] = sum;
    __syncthreads();
    for (int off = 1; off < 1024; off <<= 1) {
        int v = (t >= off) ? partial[t - off] : 0;
        __syncthreads();
        partial[t] += v;
        __syncthreads();
    }
    int run = (t == 0) ? 0 : partial[t - 1];
    for (int i = b0; i < b1; i++) {
        g_off[i] = run;
        g_cur[i] = run;
        run += g_deg[i];
    }
    if (t == 1023) g_off[NN] = run;
}

// ===== fused: layer-1 GEMM (blocks [0, G64BLK)) || CSR scatter (rest) =====
__global__ void __launch_bounds__(256)
fused_gemm1_scatter(const float* __restrict__ X, const float* __restrict__ W,
                    const float* __restrict__ a_s, const float* __restrict__ a_d,
                    const int* __restrict__ ei) {
    constexpr int IN = 128;
    constexpr int KT = 32;
    constexpr int SXS = 132;
    __shared__ float sW[KT][64];
    __shared__ float sX2[KT][SXS];
    int t = threadIdx.x;

    if (blockIdx.x >= G64BLK) {
        int e = (blockIdx.x - G64BLK) * 256 + t;
        if (e < ETOT) {
            int s, d;
            if (e < EE) { s = ei[e]; d = ei[EE + e]; } else { s = e - EE; d = s; }
            int pos = atomicAdd(&g_cur[d], 1);
            g_csr[pos] = s;
        }
        return;
    }

    int tx = t & 15, ty = t >> 4;
    int row0 = blockIdx.x * 128;
    float acc[8][4];
#pragma unroll
    for (int r = 0; r < 8; r++)
#pragma unroll
        for (int c = 0; c < 4; c++) acc[r][c] = 0.f;

    for (int kt = 0; kt < IN; kt += KT) {
#pragma unroll
        for (int i = t; i < KT * 16; i += 256) {
            int kk = i >> 4;
            int c4 = (i & 15) << 2;
            *(float4*)&sW[kk][c4] = *(const float4*)&W[(kt + kk) * 64 + c4];
        }
#pragma unroll
        for (int i = t; i < 128 * (KT / 4); i += 256) {
            int r = i >> 3;
            int k4 = (i & 7) << 2;
            int gr = row0 + r;
            float4 v = (gr < NN) ? *(const float4*)&X[gr * IN + kt + k4]
                                 : make_float4(0.f, 0.f, 0.f, 0.f);
            sX2[k4 + 0][r] = v.x;
            sX2[k4 + 1][r] = v.y;
            sX2[k4 + 2][r] = v.z;
            sX2[k4 + 3][r] = v.w;
        }
        __syncthreads();
#pragma unroll
        for (int k = 0; k < KT; k++) {
            float4 w4 = *(float4*)&sW[k][tx * 4];
            float4 xa = *(float4*)&sX2[k][ty * 8];
            float4 xb = *(float4*)&sX2[k][ty * 8 + 4];
            float xr[8] = {xa.x, xa.y, xa.z, xa.w, xb.x, xb.y, xb.z, xb.w};
#pragma unroll
            for (int r = 0; r < 8; r++) {
                acc[r][0] += xr[r] * w4.x;
                acc[r][1] += xr[r] * w4.y;
                acc[r][2] += xr[r] * w4.z;
                acc[r][3] += xr[r] * w4.w;
            }
        }
        __syncthreads();
    }

    int h = tx >> 2;
    float4 asv = *(const float4*)&a_s[h * 16 + (tx & 3) * 4];
    float4 adv = *(const float4*)&a_d[h * 16 + (tx & 3) * 4];
    __half2* h2out = (__half2*)g_h16v;
#pragma unroll
    for (int r = 0; r < 8; r++) {
        int gr = row0 + ty * 8 + r;
        float ps = acc[r][0] * asv.x + acc[r][1] * asv.y + acc[r][2] * asv.z + acc[r][3] * asv.w;
        float pd = acc[r][0] * adv.x + acc[r][1] * adv.y + acc[r][2] * adv.z + acc[r][3] * adv.w;
        ps += __shfl_xor_sync(0xffffffffu, ps, 1);
        ps += __shfl_xor_sync(0xffffffffu, ps, 2);
        pd += __shfl_xor_sync(0xffffffffu, pd, 1);
        pd += __shfl_xor_sync(0xffffffffu, pd, 2);
        if (gr < NN) {
            h2out[(gr * 64 + tx * 4) >> 1] = __floats2half2_rn(acc[r][0], acc[r][1]);
            h2out[((gr * 64 + tx * 4) >> 1) + 1] = __floats2half2_rn(acc[r][2], acc[r][3]);
            if ((tx & 3) == 0) {
                g_als[gr * 4 + h] = ps;
                g_ald[gr * 4 + h] = pd;
            }
        }
    }
}

// ------- GEMM 64-wide (layer 2), 128-row tile, fused al + fp16 out ----
template <int IN>
__global__ void __launch_bounds__(256)
gemm64(const float* __restrict__ X, const float* __restrict__ W,
       const float* __restrict__ a_s, const float* __restrict__ a_d) {
    constexpr int KT = 32;
    constexpr int SXS = 132;
    __shared__ float sW[KT][64];
    __shared__ float sX2[KT][SXS];
    int t = threadIdx.x;
    int tx = t & 15, ty = t >> 4;
    int row0 = blockIdx.x * 128;
    float acc[8][4];
#pragma unroll
    for (int r = 0; r < 8; r++)
#pragma unroll
        for (int c = 0; c < 4; c++) acc[r][c] = 0.f;

    for (int kt = 0; kt < IN; kt += KT) {
#pragma unroll
        for (int i = t; i < KT * 16; i += 256) {
            int kk = i >> 4;
            int c4 = (i & 15) << 2;
            *(float4*)&sW[kk][c4] = *(const float4*)&W[(kt + kk) * 64 + c4];
        }
#pragma unroll
        for (int i = t; i < 128 * (KT / 4); i += 256) {
            int r = i >> 3;
            int k4 = (i & 7) << 2;
            int gr = row0 + r;
            float4 v = (gr < NN) ? *(const float4*)&X[gr * IN + kt + k4]
                                 : make_float4(0.f, 0.f, 0.f, 0.f);
            sX2[k4 + 0][r] = v.x;
            sX2[k4 + 1][r] = v.y;
            sX2[k4 + 2][r] = v.z;
            sX2[k4 + 3][r] = v.w;
        }
        __syncthreads();
#pragma unroll
        for (int k = 0; k < KT; k++) {
            float4 w4 = *(float4*)&sW[k][tx * 4];
            float4 xa = *(float4*)&sX2[k][ty * 8];
            float4 xb = *(float4*)&sX2[k][ty * 8 + 4];
            float xr[8] = {xa.x, xa.y, xa.z, xa.w, xb.x, xb.y, xb.z, xb.w};
#pragma unroll
            for (int r = 0; r < 8; r++) {
                acc[r][0] += xr[r] * w4.x;
                acc[r][1] += xr[r] * w4.y;
                acc[r][2] += xr[r] * w4.z;
                acc[r][3] += xr[r] * w4.w;
            }
        }
        __syncthreads();
    }

    int h = tx >> 2;
    float4 asv = *(const float4*)&a_s[h * 16 + (tx & 3) * 4];
    float4 adv = *(const float4*)&a_d[h * 16 + (tx & 3) * 4];
    __half2* h2out = (__half2*)g_h16v;
#pragma unroll
    for (int r = 0; r < 8; r++) {
        int gr = row0 + ty * 8 + r;
        float ps = acc[r][0] * asv.x + acc[r][1] * asv.y + acc[r][2] * asv.z + acc[r][3] * asv.w;
        float pd = acc[r][0] * adv.x + acc[r][1] * adv.y + acc[r][2] * adv.z + acc[r][3] * adv.w;
        ps += __shfl_xor_sync(0xffffffffu, ps, 1);
        ps += __shfl_xor_sync(0xffffffffu, ps, 2);
        pd += __shfl_xor_sync(0xffffffffu, pd, 1);
        pd += __shfl_xor_sync(0xffffffffu, pd, 2);
        if (gr < NN) {
            h2out[(gr * 64 + tx * 4) >> 1] = __floats2half2_rn(acc[r][0], acc[r][1]);
            h2out[((gr * 64 + tx * 4) >> 1) + 1] = __floats2half2_rn(acc[r][2], acc[r][3]);
            if ((tx & 3) == 0) {
                g_als[gr * 4 + h] = ps;
                g_ald[gr * 4 + h] = pd;
            }
        }
    }
}

// ------- GEMM layer 3 (64->16): fused al epilogue, fp16-only output -------
__global__ void gemm16(const float* __restrict__ X, const float* __restrict__ W,
                       const float* __restrict__ a_s, const float* __restrict__ a_d) {
    constexpr int IN = 64, OUT = 16;
    constexpr int RB = 64;
    __shared__ float sW[IN * OUT];
    __shared__ float sX[RB * IN];
    int t = threadIdx.x;
    int tx = t & 15, ty = t >> 4;
    int row0 = blockIdx.x * RB;

    for (int i = t; i < IN * OUT; i += 256) sW[i] = W[i];
    for (int i = t; i < RB * IN; i += 256) {
        int r = row0 + i / IN;
        sX[i] = (r < NN) ? X[r * IN + (i % IN)] : 0.f;
    }
    __syncthreads();

    float acc[4];
#pragma unroll
    for (int rr = 0; rr < 4; rr++) acc[rr] = 0.f;
    const float* xs = &sX[ty * 4 * IN];
    for (int k = 0; k < IN; k++) {
        float wv = sW[k * OUT + tx];
#pragma unroll
        for (int rr = 0; rr < 4; rr++) acc[rr] += xs[rr * IN + k] * wv;
    }
    float asx = __ldg(&a_s[tx]), adx = __ldg(&a_d[tx]);
    __half* h16 = (__half*)g_h16v;
#pragma unroll
    for (int rr = 0; rr < 4; rr++) {
        int r = row0 + ty * 4 + rr;
        float ps = acc[rr] * asx;
        float pd = acc[rr] * adx;
#pragma unroll
        for (int off = 1; off < 16; off <<= 1) {
            ps += __shfl_xor_sync(0xffffffffu, ps, off);
            pd += __shfl_xor_sync(0xffffffffu, pd, off);
        }
        if (r < NN) {
            h16[r * OUT + tx] = __float2half_rn(acc[rr]);
            if (tx == 0) {
                g_als[r] = ps;
                g_ald[r] = pd;
            }
        }
    }
}

__device__ __forceinline__ float lrelu_exp(float v) {
    v = (v > 0.f) ? v : 0.2f * v;
    return __expf(v);
}

// ============ fused gather-aggregation, 64-wide (layers 1 & 2) ============
// warp per dst node; lane owns half2 cols (2*lane, 2*lane+1), head = lane>>3.
// (s*32, ex) packed as float2 in smem -> 1 LDS.64 + IADD-only addressing.
__global__ void __launch_bounds__(256)
agg64(const float* __restrict__ b,
      const float* __restrict__ gg, const float* __restrict__ bb,
      const float* __restrict__ mm, const float* __restrict__ vv,
      float* __restrict__ xnext) {
    __shared__ float2 sh_sex[8][4][33];
    int w = threadIdx.x >> 5;
    int lane = threadIdx.x & 31;
    int n = (blockIdx.x * blockDim.x + threadIdx.x) >> 5;
    if (n >= NN) return;
    int c0 = 2 * lane;
    int h = lane >> 3;
    float4 ad4 = *(const float4*)&g_ald[n * 4];
    float accx = 0.f, accy = 0.f, den = 0.f;
    const __half2* ph2 = (const __half2*)g_h16v;
    int beg = g_off[n], end = g_off[n + 1];
    for (int base = beg; base < end; base += 32) {
        int idx = base + lane;
        bool valid = idx < end;
        int s = valid ? g_csr[idx] : 0;
        float4 as4 = *(const float4*)&g_als[s * 4];
        float sf = __int_as_float(s * 32);     // pre-multiplied row base (half2 units)
        float e0 = valid ? lrelu_exp(as4.x + ad4.x) : 0.f;
        float e1 = valid ? lrelu_exp(as4.y + ad4.y) : 0.f;
        float e2 = valid ? lrelu_exp(as4.z + ad4.z) : 0.f;
        float e3 = valid ? lrelu_exp(as4.w + ad4.w) : 0.f;
        __syncwarp();
        sh_sex[w][0][lane] = make_float2(sf, e0);
        sh_sex[w][1][lane] = make_float2(sf, e1);
        sh_sex[w][2][lane] = make_float2(sf, e2);
        sh_sex[w][3][lane] = make_float2(sf, e3);
        __syncwarp();
        int nk8 = (min(32, end - base) + 7) & ~7;
        for (int j0 = 0; j0 < nk8; j0 += 8) {
#pragma unroll
            for (int jj = 0; jj < 8; jj++) {
                int j = j0 + jj;
                float2 p = sh_sex[w][h][j];
                int sj32 = __float_as_int(p.x);
                float ex = p.y;
                float2 f = __half22float2(__ldg(&ph2[sj32 + lane]));
                accx += ex * f.x;
                accy += ex * f.y;
                den += ex;
            }
        }
    }
    float inv = 1.f / (den + 1e-16f);
    float r0 = accx * inv;
    float r1 = accy * inv;
    int c1 = c0 + 1;
    float y0 = (r0 + __ldg(&b[c0]) - __ldg(&mm[c0])) * rsqrtf(__ldg(&vv[c0]) + 1e-5f) *
                   __ldg(&gg[c0]) + __ldg(&bb[c0]);
    float y1 = (r1 + __ldg(&b[c1]) - __ldg(&mm[c1])) * rsqrtf(__ldg(&vv[c1]) + 1e-5f) *
                   __ldg(&gg[c1]) + __ldg(&bb[c1]);
    float2 o = make_float2(fmaxf(y0, 0.f), fmaxf(y1, 0.f));
    *(float2*)&xnext[n * 64 + c0] = o;
}

// ============ fused gather-aggregation, 16-wide (layer 3) ============
__global__ void __launch_bounds__(256)
agg16() {
    __shared__ float2 sh_sex[8][33];
    int w = threadIdx.x >> 5;
    int lane = threadIdx.x & 31;
    int n = (blockIdx.x * blockDim.x + threadIdx.x) >> 5;
    if (n >= NN) return;
    int q = lane >> 3;        // edge-group 0..3
    int c2 = lane & 7;        // half2 column index
    float ad = g_ald[n];
    float accx = 0.f, accy = 0.f, den = 0.f;
    const __half2* ph2 = (const __half2*)g_h16v;
    int beg = g_off[n], end = g_off[n + 1];
    for (int base = beg; base < end; base += 32) {
        int idx = base + lane;
        bool valid = idx < end;
        int s = valid ? g_csr[idx] : 0;
        float ex = valid ? lrelu_exp(__ldg(&g_als[s]) + ad) : 0.f;
        __syncwarp();
        sh_sex[w][lane] = make_float2(__int_as_float(s * 8), ex);
        __syncwarp();
        int nk4 = (min(32, end - base) + 3) & ~3;
        for (int j0 = 0; j0 < nk4; j0 += 4) {
            int j = j0 + q;
            float2 p = sh_sex[w][j];
            int sj8 = __float_as_int(p.x);
            float exj = p.y;
            float2 f = __half22float2(__ldg(&ph2[sj8 + c2]));
            accx += exj * f.x;
            accy += exj * f.y;
            den += exj;
        }
    }
    accx += __shfl_xor_sync(0xffffffffu, accx, 8);
    accx += __shfl_xor_sync(0xffffffffu, accx, 16);
    accy += __shfl_xor_sync(0xffffffffu, accy, 8);
    accy += __shfl_xor_sync(0xffffffffu, accy, 16);
    den += __shfl_xor_sync(0xffffffffu, den, 8);
    den += __shfl_xor_sync(0xffffffffu, den, 16);
    if (lane < 8) {
        float inv = 1.f / (den + 1e-16f);
        float2 o = make_float2(accx * inv, accy * inv);
        *(float2*)&g_acc[n * 16 + 2 * c2] = o;
    }
}

// ---------------- epilogue layer 3 ----------------
__global__ void ep3(const float* __restrict__ b3, const float* __restrict__ gg,
                    const float* __restrict__ bb, const float* __restrict__ mm,
                    const float* __restrict__ vv, const float* __restrict__ fw1,
                    const float* __restrict__ fb1, const float* __restrict__ fw2,
                    const float* __restrict__ fb2, float* __restrict__ out) {
    int n = blockIdx.x * blockDim.x + threadIdx.x;
    if (n >= NN) return;
    float t[16];
#pragma unroll
    for (int c = 0; c < 16; c++) {
        float y = (g_acc[n * 16 + c] + __ldg(&b3[c]) - __ldg(&mm[c])) *
                      rsqrtf(__ldg(&vv[c]) + 1e-5f) * __ldg(&gg[c]) +
                  __ldg(&bb[c]);
        t[c] = fmaxf(y, 0.f);
    }
    float o = __ldg(&fb2[0]);
#pragma unroll
    for (int oo = 0; oo < 8; oo++) {
        float z = __ldg(&fb1[oo]);
#pragma unroll
        for (int c = 0; c < 16; c++) z += t[c] * __ldg(&fw1[c * 8 + oo]);
        z = fmaxf(z, 0.f);
        o += z * __ldg(&fw2[oo]);
    }
    out[n] = o;
}

// ---------------- launch ----------------
extern "C" void kernel_launch(void* const* d_in, const int* in_sizes, int n_in,
                              void* d_out, int out_size) {
    const float* x = (const float*)d_in[0];
    const int* ei = (const int*)d_in[1];
    const float* W1 = (const float*)d_in[2];
    const float* as1 = (const float*)d_in[3];
    const float* ad1 = (const float*)d_in[4];
    const float* b1 = (const float*)d_in[5];
    const float* g1 = (const float*)d_in[6];
    const float* bb1 = (const float*)d_in[7];
    const float* m1 = (const float*)d_in[8];
    const float* v1 = (const float*)d_in[9];
    const float* W2 = (const float*)d_in[10];
    const float* as2 = (const float*)d_in[11];
    const float* ad2 = (const float*)d_in[12];
    const float* b2 = (const float*)d_in[13];
    const float* g2 = (const float*)d_in[14];
    const float* bb2 = (const float*)d_in[15];
    const float* m2 = (const float*)d_in[16];
    const float* v2 = (const float*)d_in[17];
    const float* W3 = (const float*)d_in[18];
    const float* as3 = (const float*)d_in[19];
    const float* ad3 = (const float*)d_in[20];
    const float* b3 = (const float*)d_in[21];
    const float* g3 = (const float*)d_in[22];
    const float* bb3 = (const float*)d_in[23];
    const float* m3 = (const float*)d_in[24];
    const float* v3 = (const float*)d_in[25];
    const float* fw1 = (const float*)d_in[26];
    const float* fb1 = (const float*)d_in[27];
    const float* fw2 = (const float*)d_in[28];
    const float* fb2 = (const float*)d_in[29];
    float* out = (float*)d_out;

    float* px2 = nullptr;
    int* pdeg = nullptr;
    cudaGetSymbolAddress((void**)&px2, g_x2);
    cudaGetSymbolAddress((void**)&pdeg, g_deg);

    const int TB = 256;
    int nblk = (NN + TB - 1) / TB;
    int aggblk = (NN * 32 + TB - 1) / TB;

    // ---- CSR: hist + scan, then scatter fused with layer-1 GEMM ----
    cudaMemsetAsync(pdeg, 0, NN * sizeof(int));
    hist_kernel<<<EBLK, TB>>>(ei);
    scan_kernel<<<1, 1024>>>();

    // ---- Layer 1 GEMM || CSR scatter ----
    fused_gemm1_scatter<<<G64BLK + EBLK, TB>>>(x, W1, as1, ad1, ei);
    agg64<<<aggblk, TB>>>(b1, g1, bb1, m1, v1, px2);

    // ---- Layer 2 ----
    gemm64<64><<<G64BLK, TB>>>(px2, W2, as2, ad2);
    agg64<<<aggblk, TB>>>(b2, g2, bb2, m2, v2, px2);

    // ---- Layer 3 ----
    gemm16<<<(NN + 63) / 64, TB>>>(px2, W3, as3, ad3);
    agg16<<<aggblk, TB>>>();
    ep3<<<nblk, TB>>>(b3, g3, bb3, m3, v3, fw1, fb1, fw2, fb2, out);
}

// round 11
// speedup vs baseline: 1.0841x; 1.0160x over previous
#include <cuda_runtime.h>
#include <cuda_fp16.h>
#include <math.h>

#define NN 50000
#define EE 1600000
#define ETOT (EE + NN)
#define G64BLK ((NN + 127) / 128)
#define EBLK ((ETOT + 255) / 256)

// ---------------- scratch ----------------
__device__ uint4  g_h16v[NN * 8];    // fp16 h, 16B-aligned (64 halves per node)
__device__ float  g_x2[NN * 64];
__device__ float  g_als[NN * 4];
__device__ float  g_ald[NN * 4];
__device__ float  g_acc[NN * 16];
__device__ int    g_deg[NN];
__device__ int    g_off[NN + 1];
__device__ int    g_cur[NN];
__device__ int    g_csr[ETOT];

// ================= CSR build =================
__global__ void hist_kernel(const int* __restrict__ ei) {
    int e = blockIdx.x * blockDim.x + threadIdx.x;
    if (e >= ETOT) return;
    int d = (e < EE) ? ei[EE + e] : (e - EE);
    atomicAdd(&g_deg[d], 1);
}

__global__ void scan_kernel() {
    __shared__ int partial[1024];
    int t = threadIdx.x;
    const int C = (NN + 1023) / 1024;
    int b0 = t * C;
    int b1 = min(b0 + C, NN);
    int sum = 0;
    for (int i = b0; i < b1; i++) sum += g_deg[i];
    partial[t] = sum;
    __syncthreads();
    for (int off = 1; off < 1024; off <<= 1) {
        int v = (t >= off) ? partial[t - off] : 0;
        __syncthreads();
        partial[t] += v;
        __syncthreads();
    }
    int run = (t == 0) ? 0 : partial[t - 1];
    for (int i = b0; i < b1; i++) {
        g_off[i] = run;
        g_cur[i] = run;
        run += g_deg[i];
    }
    if (t == 1023) g_off[NN] = run;
}

// ===== fused: layer-1 GEMM (blocks [0, G64BLK)) || CSR scatter (rest) =====
__global__ void __launch_bounds__(256)
fused_gemm1_scatter(const float* __restrict__ X, const float* __restrict__ W,
                    const float* __restrict__ a_s, const float* __restrict__ a_d,
                    const int* __restrict__ ei) {
    constexpr int IN = 128;
    constexpr int KT = 32;
    constexpr int SXS = 132;
    __shared__ float sW[KT][64];
    __shared__ float sX2[KT][SXS];
    int t = threadIdx.x;

    if (blockIdx.x >= G64BLK) {
        int e = (blockIdx.x - G64BLK) * 256 + t;
        if (e < ETOT) {
            int s, d;
            if (e < EE) { s = ei[e]; d = ei[EE + e]; } else { s = e - EE; d = s; }
            int pos = atomicAdd(&g_cur[d], 1);
            g_csr[pos] = s;
        }
        return;
    }

    int tx = t & 15, ty = t >> 4;
    int row0 = blockIdx.x * 128;
    float acc[8][4];
#pragma unroll
    for (int r = 0; r < 8; r++)
#pragma unroll
        for (int c = 0; c < 4; c++) acc[r][c] = 0.f;

    for (int kt = 0; kt < IN; kt += KT) {
#pragma unroll
        for (int i = t; i < KT * 16; i += 256) {
            int kk = i >> 4;
            int c4 = (i & 15) << 2;
            *(float4*)&sW[kk][c4] = *(const float4*)&W[(kt + kk) * 64 + c4];
        }
#pragma unroll
        for (int i = t; i < 128 * (KT / 4); i += 256) {
            int r = i >> 3;
            int k4 = (i & 7) << 2;
            int gr = row0 + r;
            float4 v = (gr < NN) ? *(const float4*)&X[gr * IN + kt + k4]
                                 : make_float4(0.f, 0.f, 0.f, 0.f);
            sX2[k4 + 0][r] = v.x;
            sX2[k4 + 1][r] = v.y;
            sX2[k4 + 2][r] = v.z;
            sX2[k4 + 3][r] = v.w;
        }
        __syncthreads();
#pragma unroll
        for (int k = 0; k < KT; k++) {
            float4 w4 = *(float4*)&sW[k][tx * 4];
            float4 xa = *(float4*)&sX2[k][ty * 8];
            float4 xb = *(float4*)&sX2[k][ty * 8 + 4];
            float xr[8] = {xa.x, xa.y, xa.z, xa.w, xb.x, xb.y, xb.z, xb.w};
#pragma unroll
            for (int r = 0; r < 8; r++) {
                acc[r][0] += xr[r] * w4.x;
                acc[r][1] += xr[r] * w4.y;
                acc[r][2] += xr[r] * w4.z;
                acc[r][3] += xr[r] * w4.w;
            }
        }
        __syncthreads();
    }

    int h = tx >> 2;
    float4 asv = *(const float4*)&a_s[h * 16 + (tx & 3) * 4];
    float4 adv = *(const float4*)&a_d[h * 16 + (tx & 3) * 4];
    __half2* h2out = (__half2*)g_h16v;
#pragma unroll
    for (int r = 0; r < 8; r++) {
        int gr = row0 + ty * 8 + r;
        float ps = acc[r][0] * asv.x + acc[r][1] * asv.y + acc[r][2] * asv.z + acc[r][3] * asv.w;
        float pd = acc[r][0] * adv.x + acc[r][1] * adv.y + acc[r][2] * adv.z + acc[r][3] * adv.w;
        ps += __shfl_xor_sync(0xffffffffu, ps, 1);
        ps += __shfl_xor_sync(0xffffffffu, ps, 2);
        pd += __shfl_xor_sync(0xffffffffu, pd, 1);
        pd += __shfl_xor_sync(0xffffffffu, pd, 2);
        if (gr < NN) {
            h2out[(gr * 64 + tx * 4) >> 1] = __floats2half2_rn(acc[r][0], acc[r][1]);
            h2out[((gr * 64 + tx * 4) >> 1) + 1] = __floats2half2_rn(acc[r][2], acc[r][3]);
            if ((tx & 3) == 0) {
                g_als[gr * 4 + h] = ps;
                g_ald[gr * 4 + h] = pd;
            }
        }
    }
}

// ------- GEMM 64-wide (layer 2), 128-row tile, fused al + fp16 out ----
template <int IN>
__global__ void __launch_bounds__(256)
gemm64(const float* __restrict__ X, const float* __restrict__ W,
       const float* __restrict__ a_s, const float* __restrict__ a_d) {
    constexpr int KT = 32;
    constexpr int SXS = 132;
    __shared__ float sW[KT][64];
    __shared__ float sX2[KT][SXS];
    int t = threadIdx.x;
    int tx = t & 15, ty = t >> 4;
    int row0 = blockIdx.x * 128;
    float acc[8][4];
#pragma unroll
    for (int r = 0; r < 8; r++)
#pragma unroll
        for (int c = 0; c < 4; c++) acc[r][c] = 0.f;

    for (int kt = 0; kt < IN; kt += KT) {
#pragma unroll
        for (int i = t; i < KT * 16; i += 256) {
            int kk = i >> 4;
            int c4 = (i & 15) << 2;
            *(float4*)&sW[kk][c4] = *(const float4*)&W[(kt + kk) * 64 + c4];
        }
#pragma unroll
        for (int i = t; i < 128 * (KT / 4); i += 256) {
            int r = i >> 3;
            int k4 = (i & 7) << 2;
            int gr = row0 + r;
            float4 v = (gr < NN) ? *(const float4*)&X[gr * IN + kt + k4]
                                 : make_float4(0.f, 0.f, 0.f, 0.f);
            sX2[k4 + 0][r] = v.x;
            sX2[k4 + 1][r] = v.y;
            sX2[k4 + 2][r] = v.z;
            sX2[k4 + 3][r] = v.w;
        }
        __syncthreads();
#pragma unroll
        for (int k = 0; k < KT; k++) {
            float4 w4 = *(float4*)&sW[k][tx * 4];
            float4 xa = *(float4*)&sX2[k][ty * 8];
            float4 xb = *(float4*)&sX2[k][ty * 8 + 4];
            float xr[8] = {xa.x, xa.y, xa.z, xa.w, xb.x, xb.y, xb.z, xb.w};
#pragma unroll
            for (int r = 0; r < 8; r++) {
                acc[r][0] += xr[r] * w4.x;
                acc[r][1] += xr[r] * w4.y;
                acc[r][2] += xr[r] * w4.z;
                acc[r][3] += xr[r] * w4.w;
            }
        }
        __syncthreads();
    }

    int h = tx >> 2;
    float4 asv = *(const float4*)&a_s[h * 16 + (tx & 3) * 4];
    float4 adv = *(const float4*)&a_d[h * 16 + (tx & 3) * 4];
    __half2* h2out = (__half2*)g_h16v;
#pragma unroll
    for (int r = 0; r < 8; r++) {
        int gr = row0 + ty * 8 + r;
        float ps = acc[r][0] * asv.x + acc[r][1] * asv.y + acc[r][2] * asv.z + acc[r][3] * asv.w;
        float pd = acc[r][0] * adv.x + acc[r][1] * adv.y + acc[r][2] * adv.z + acc[r][3] * adv.w;
        ps += __shfl_xor_sync(0xffffffffu, ps, 1);
        ps += __shfl_xor_sync(0xffffffffu, ps, 2);
        pd += __shfl_xor_sync(0xffffffffu, pd, 1);
        pd += __shfl_xor_sync(0xffffffffu, pd, 2);
        if (gr < NN) {
            h2out[(gr * 64 + tx * 4) >> 1] = __floats2half2_rn(acc[r][0], acc[r][1]);
            h2out[((gr * 64 + tx * 4) >> 1) + 1] = __floats2half2_rn(acc[r][2], acc[r][3]);
            if ((tx & 3) == 0) {
                g_als[gr * 4 + h] = ps;
                g_ald[gr * 4 + h] = pd;
            }
        }
    }
}

// ------- GEMM layer 3 (64->16): fused al epilogue, fp16-only output -------
__global__ void gemm16(const float* __restrict__ X, const float* __restrict__ W,
                       const float* __restrict__ a_s, const float* __restrict__ a_d) {
    constexpr int IN = 64, OUT = 16;
    constexpr int RB = 64;
    __shared__ float sW[IN * OUT];
    __shared__ float sX[RB * IN];
    int t = threadIdx.x;
    int tx = t & 15, ty = t >> 4;
    int row0 = blockIdx.x * RB;

    for (int i = t; i < IN * OUT; i += 256) sW[i] = W[i];
    for (int i = t; i < RB * IN; i += 256) {
        int r = row0 + i / IN;
        sX[i] = (r < NN) ? X[r * IN + (i % IN)] : 0.f;
    }
    __syncthreads();

    float acc[4];
#pragma unroll
    for (int rr = 0; rr < 4; rr++) acc[rr] = 0.f;
    const float* xs = &sX[ty * 4 * IN];
    for (int k = 0; k < IN; k++) {
        float wv = sW[k * OUT + tx];
#pragma unroll
        for (int rr = 0; rr < 4; rr++) acc[rr] += xs[rr * IN + k] * wv;
    }
    float asx = __ldg(&a_s[tx]), adx = __ldg(&a_d[tx]);
    __half* h16 = (__half*)g_h16v;
#pragma unroll
    for (int rr = 0; rr < 4; rr++) {
        int r = row0 + ty * 4 + rr;
        float ps = acc[rr] * asx;
        float pd = acc[rr] * adx;
#pragma unroll
        for (int off = 1; off < 16; off <<= 1) {
            ps += __shfl_xor_sync(0xffffffffu, ps, off);
            pd += __shfl_xor_sync(0xffffffffu, pd, off);
        }
        if (r < NN) {
            h16[r * OUT + tx] = __float2half_rn(acc[rr]);
            if (tx == 0) {
                g_als[r] = ps;
                g_ald[r] = pd;
            }
        }
    }
}

__device__ __forceinline__ float lrelu_exp(float v) {
    v = (v > 0.f) ? v : 0.2f * v;
    return __expf(v);
}

// ============ fused gather-aggregation, 64-wide (layers 1 & 2) ============
// warp per dst node; 2 edge-halves of 16 lanes; lane owns 4 cols via LDG.64.
// head = (lane&15)>>2. (s*16, ex) packed float2 in smem, [4][34] padding
// makes the two-edge-offset reads conflict-free. Unroll 4 => MLP 4.
__global__ void __launch_bounds__(256)
agg64(const float* __restrict__ b,
      const float* __restrict__ gg, const float* __restrict__ bb,
      const float* __restrict__ mm, const float* __restrict__ vv,
      float* __restrict__ xnext) {
    __shared__ float2 sh_sex[8][4][34];
    int w = threadIdx.x >> 5;
    int lane = threadIdx.x & 31;
    int n = (blockIdx.x * blockDim.x + threadIdx.x) >> 5;
    if (n >= NN) return;
    int eg = lane >> 4;        // edge half 0/1
    int cq = lane & 15;        // col quad: cols 4*cq .. 4*cq+3
    int h = cq >> 2;           // head of those cols
    float4 ad4 = *(const float4*)&g_ald[n * 4];
    float acc0 = 0.f, acc1 = 0.f, acc2 = 0.f, acc3 = 0.f, den = 0.f;
    const uint2* pu2 = (const uint2*)g_h16v;
    int beg = g_off[n], end = g_off[n + 1];
    for (int base = beg; base < end; base += 32) {
        int idx = base + lane;
        bool valid = idx < end;
        int s = valid ? g_csr[idx] : 0;
        float4 as4 = *(const float4*)&g_als[s * 4];
        float sf = __int_as_float(s * 16);     // row base in uint2 units
        float e0 = valid ? lrelu_exp(as4.x + ad4.x) : 0.f;
        float e1 = valid ? lrelu_exp(as4.y + ad4.y) : 0.f;
        float e2 = valid ? lrelu_exp(as4.z + ad4.z) : 0.f;
        float e3 = valid ? lrelu_exp(as4.w + ad4.w) : 0.f;
        __syncwarp();
        sh_sex[w][0][lane] = make_float2(sf, e0);
        sh_sex[w][1][lane] = make_float2(sf, e1);
        sh_sex[w][2][lane] = make_float2(sf, e2);
        sh_sex[w][3][lane] = make_float2(sf, e3);
        __syncwarp();
        int nk8 = (min(32, end - base) + 7) & ~7;
        for (int j0 = 0; j0 < nk8; j0 += 8) {
#pragma unroll
            for (int u = 0; u < 4; u++) {
                int j = j0 + 2 * u + eg;
                float2 p = sh_sex[w][h][j];
                int sj16 = __float_as_int(p.x);
                float ex = p.y;
                uint2 v = __ldg(&pu2[sj16 + cq]);
                float2 f0 = __half22float2(*(__half2*)&v.x);
                float2 f1 = __half22float2(*(__half2*)&v.y);
                acc0 += ex * f0.x;
                acc1 += ex * f0.y;
                acc2 += ex * f1.x;
                acc3 += ex * f1.y;
                den += ex;
            }
        }
    }
    // combine the two edge halves
    acc0 += __shfl_xor_sync(0xffffffffu, acc0, 16);
    acc1 += __shfl_xor_sync(0xffffffffu, acc1, 16);
    acc2 += __shfl_xor_sync(0xffffffffu, acc2, 16);
    acc3 += __shfl_xor_sync(0xffffffffu, acc3, 16);
    den += __shfl_xor_sync(0xffffffffu, den, 16);
    if (lane < 16) {
        float inv = 1.f / (den + 1e-16f);
        int c0 = 4 * cq;
        float a[4] = {acc0 * inv, acc1 * inv, acc2 * inv, acc3 * inv};
        float o[4];
#pragma unroll
        for (int i = 0; i < 4; i++) {
            int col = c0 + i;
            float y = (a[i] + __ldg(&b[col]) - __ldg(&mm[col])) *
                          rsqrtf(__ldg(&vv[col]) + 1e-5f) * __ldg(&gg[col]) +
                      __ldg(&bb[col]);
            o[i] = fmaxf(y, 0.f);
        }
        *(float4*)&xnext[n * 64 + c0] = make_float4(o[0], o[1], o[2], o[3]);
    }
}

// ============ fused gather-aggregation, 16-wide (layer 3) ============
__global__ void __launch_bounds__(256)
agg16() {
    __shared__ float2 sh_sex[8][33];
    int w = threadIdx.x >> 5;
    int lane = threadIdx.x & 31;
    int n = (blockIdx.x * blockDim.x + threadIdx.x) >> 5;
    if (n >= NN) return;
    int q = lane >> 3;        // edge-group 0..3
    int c2 = lane & 7;        // half2 column index
    float ad = g_ald[n];
    float accx = 0.f, accy = 0.f, den = 0.f;
    const __half2* ph2 = (const __half2*)g_h16v;
    int beg = g_off[n], end = g_off[n + 1];
    for (int base = beg; base < end; base += 32) {
        int idx = base + lane;
        bool valid = idx < end;
        int s = valid ? g_csr[idx] : 0;
        float ex = valid ? lrelu_exp(__ldg(&g_als[s]) + ad) : 0.f;
        __syncwarp();
        sh_sex[w][lane] = make_float2(__int_as_float(s * 8), ex);
        __syncwarp();
        int nk4 = (min(32, end - base) + 3) & ~3;
        for (int j0 = 0; j0 < nk4; j0 += 4) {
            int j = j0 + q;
            float2 p = sh_sex[w][j];
            int sj8 = __float_as_int(p.x);
            float exj = p.y;
            float2 f = __half22float2(__ldg(&ph2[sj8 + c2]));
            accx += exj * f.x;
            accy += exj * f.y;
            den += exj;
        }
    }
    accx += __shfl_xor_sync(0xffffffffu, accx, 8);
    accx += __shfl_xor_sync(0xffffffffu, accx, 16);
    accy += __shfl_xor_sync(0xffffffffu, accy, 8);
    accy += __shfl_xor_sync(0xffffffffu, accy, 16);
    den += __shfl_xor_sync(0xffffffffu, den, 8);
    den += __shfl_xor_sync(0xffffffffu, den, 16);
    if (lane < 8) {
        float inv = 1.f / (den + 1e-16f);
        float2 o = make_float2(accx * inv, accy * inv);
        *(float2*)&g_acc[n * 16 + 2 * c2] = o;
    }
}

// ---------------- epilogue layer 3 ----------------
__global__ void ep3(const float* __restrict__ b3, const float* __restrict__ gg,
                    const float* __restrict__ bb, const float* __restrict__ mm,
                    const float* __restrict__ vv, const float* __restrict__ fw1,
                    const float* __restrict__ fb1, const float* __restrict__ fw2,
                    const float* __restrict__ fb2, float* __restrict__ out) {
    int n = blockIdx.x * blockDim.x + threadIdx.x;
    if (n >= NN) return;
    float t[16];
#pragma unroll
    for (int c = 0; c < 16; c++) {
        float y = (g_acc[n * 16 + c] + __ldg(&b3[c]) - __ldg(&mm[c])) *
                      rsqrtf(__ldg(&vv[c]) + 1e-5f) * __ldg(&gg[c]) +
                  __ldg(&bb[c]);
        t[c] = fmaxf(y, 0.f);
    }
    float o = __ldg(&fb2[0]);
#pragma unroll
    for (int oo = 0; oo < 8; oo++) {
        float z = __ldg(&fb1[oo]);
#pragma unroll
        for (int c = 0; c < 16; c++) z += t[c] * __ldg(&fw1[c * 8 + oo]);
        z = fmaxf(z, 0.f);
        o += z * __ldg(&fw2[oo]);
    }
    out[n] = o;
}

// ---------------- launch ----------------
extern "C" void kernel_launch(void* const* d_in, const int* in_sizes, int n_in,
                              void* d_out, int out_size) {
    const float* x = (const float*)d_in[0];
    const int* ei = (const int*)d_in[1];
    const float* W1 = (const float*)d_in[2];
    const float* as1 = (const float*)d_in[3];
    const float* ad1 = (const float*)d_in[4];
    const float* b1 = (const float*)d_in[5];
    const float* g1 = (const float*)d_in[6];
    const float* bb1 = (const float*)d_in[7];
    const float* m1 = (const float*)d_in[8];
    const float* v1 = (const float*)d_in[9];
    const float* W2 = (const float*)d_in[10];
    const float* as2 = (const float*)d_in[11];
    const float* ad2 = (const float*)d_in[12];
    const float* b2 = (const float*)d_in[13];
    const float* g2 = (const float*)d_in[14];
    const float* bb2 = (const float*)d_in[15];
    const float* m2 = (const float*)d_in[16];
    const float* v2 = (const float*)d_in[17];
    const float* W3 = (const float*)d_in[18];
    const float* as3 = (const float*)d_in[19];
    const float* ad3 = (const float*)d_in[20];
    const float* b3 = (const float*)d_in[21];
    const float* g3 = (const float*)d_in[22];
    const float* bb3 = (const float*)d_in[23];
    const float* m3 = (const float*)d_in[24];
    const float* v3 = (const float*)d_in[25];
    const float* fw1 = (const float*)d_in[26];
    const float* fb1 = (const float*)d_in[27];
    const float* fw2 = (const float*)d_in[28];
    const float* fb2 = (const float*)d_in[29];
    float* out = (float*)d_out;

    float* px2 = nullptr;
    int* pdeg = nullptr;
    cudaGetSymbolAddress((void**)&px2, g_x2);
    cudaGetSymbolAddress((void**)&pdeg, g_deg);

    const int TB = 256;
    int nblk = (NN + TB - 1) / TB;
    int aggblk = (NN * 32 + TB - 1) / TB;

    // ---- CSR: hist + scan, then scatter fused with layer-1 GEMM ----
    cudaMemsetAsync(pdeg, 0, NN * sizeof(int));
    hist_kernel<<<EBLK, TB>>>(ei);
    scan_kernel<<<1, 1024>>>();

    // ---- Layer 1 GEMM || CSR scatter ----
    fused_gemm1_scatter<<<G64BLK + EBLK, TB>>>(x, W1, as1, ad1, ei);
    agg64<<<aggblk, TB>>>(b1, g1, bb1, m1, v1, px2);

    // ---- Layer 2 ----
    gemm64<64><<<G64BLK, TB>>>(px2, W2, as2, ad2);
    agg64<<<aggblk, TB>>>(b2, g2, bb2, m2, v2, px2);

    // ---- Layer 3 ----
    gemm16<<<(NN + 63) / 64, TB>>>(px2, W3, as3, ad3);
    agg16<<<aggblk, TB>>>();
    ep3<<<nblk, TB>>>(b3, g3, bb3, m3, v3, fw1, fb1, fw2, fb2, out);
}